// round 10
// baseline (speedup 1.0000x reference)
#include <cuda_runtime.h>
#include <cuda_fp16.h>
#include <math.h>
#include <stdint.h>

#define BATCH 4
#define SEQ   4096
#define DIM   512
#define MTOT  (BATCH * SEQ)
#define NTILE (SEQ / 64)
#define NEG_INF __int_as_float(0xff800000)

// ---------------- scratch (static device globals; no allocation) ------------
__device__ __half g_Xh [(size_t)MTOT * DIM];
__device__ int8_t g_Xr8[(size_t)MTOT * DIM];   // round((X - Xh) * 2^15)
__device__ int8_t g_Xh8[(size_t)MTOT * DIM];   // round(X * 16)
__device__ __half g_Wh [3][DIM * DIM];
__device__ int8_t g_Wr8[3][DIM * DIM];         // round((W - Wh) * 2^22)
__device__ int8_t g_Wh8[3][DIM * DIM];         // round(W * 2048)
__device__ __half g_Qh [(size_t)MTOT * DIM];
__device__ int8_t g_Qr8[(size_t)MTOT * DIM];   // round((Q - Qh) * 2^16)
__device__ int8_t g_Qh8[(size_t)MTOT * DIM];   // round(Q * 32)
__device__ __half g_Kh [(size_t)MTOT * DIM];
__device__ int8_t g_Kr8[(size_t)MTOT * DIM];
__device__ int8_t g_Kh8[(size_t)MTOT * DIM];
__device__ __half g_Vth[(size_t)DIM * MTOT];   // V^T hi plane only
__device__ float  g_S [(size_t)BATCH * SEQ * SEQ];
__device__ __half g_Ph[(size_t)BATCH * SEQ * SEQ];
__device__ float  g_cm[(size_t)NTILE * BATCH * SEQ];
__device__ float  g_cz[(size_t)NTILE * BATCH * SEQ];
__device__ float  g_m [(size_t)BATCH * SEQ];
__device__ float  g_rz[(size_t)BATCH * SEQ];

// ---------------- fast exp on the FMA pipe -----------------------------------
__device__ __forceinline__ float fast_exp(float x) {
    x = fmaxf(x, -80.0f);
    const float y  = x * 1.4426950408889634f;
    const float t  = y + 12582912.0f;
    const int   ni = __float_as_int(t) - 0x4B400000;
    const float f  = y - (t - 12582912.0f);
    float p = 1.3333558146e-3f;
    p = fmaf(p, f, 9.6181291076e-3f);
    p = fmaf(p, f, 5.5504108664e-2f);
    p = fmaf(p, f, 2.4022650696e-1f);
    p = fmaf(p, f, 6.9314718056e-1f);
    p = fmaf(p, f, 1.0f);
    return __int_as_float(__float_as_int(p) + (ni << 23));
}

__device__ __forceinline__ int8_t q8(float x) {
    x = fminf(fmaxf(x, -127.f), 127.f);
    return (int8_t)__float2int_rn(x);
}

// ============================ PTX helpers ===================================
__device__ __forceinline__ uint32_t smem_u32(const void* p) {
    uint32_t a;
    asm("{ .reg .u64 t; cvta.to.shared.u64 t, %1; cvt.u32.u64 %0, t; }"
        : "=r"(a) : "l"(p));
    return a;
}
template<int N> __device__ __forceinline__ void cp_wait() {
    asm volatile("cp.async.wait_group %0;" :: "n"(N) : "memory");
}
__device__ __forceinline__ void cp_commit() {
    asm volatile("cp.async.commit_group;" ::: "memory");
}
__device__ __forceinline__ void cp16(uint32_t dst, const void* src) {
    asm volatile("cp.async.cg.shared.global [%0], [%1], 16;"
                 :: "r"(dst), "l"(src) : "memory");
}
__device__ __forceinline__ void ldsm4(uint32_t* r, uint32_t a) {
    asm volatile("ldmatrix.sync.aligned.m8n8.x4.shared.b16 {%0,%1,%2,%3}, [%4];"
                 : "=r"(r[0]), "=r"(r[1]), "=r"(r[2]), "=r"(r[3]) : "r"(a));
}
__device__ __forceinline__ void mma16816(float* d, const uint32_t* a,
                                         uint32_t b0, uint32_t b1) {
    asm volatile("mma.sync.aligned.m16n8k16.row.col.f32.f16.f16.f32 "
                 "{%0,%1,%2,%3},{%4,%5,%6,%7},{%8,%9},{%0,%1,%2,%3};"
                 : "+f"(d[0]), "+f"(d[1]), "+f"(d[2]), "+f"(d[3])
                 : "r"(a[0]), "r"(a[1]), "r"(a[2]), "r"(a[3]), "r"(b0), "r"(b1));
}
__device__ __forceinline__ void mma_s8(int* d, const uint32_t* a,
                                       uint32_t b0, uint32_t b1) {
    asm volatile("mma.sync.aligned.m16n8k32.row.col.s32.s8.s8.s32 "
                 "{%0,%1,%2,%3},{%4,%5,%6,%7},{%8,%9},{%0,%1,%2,%3};"
                 : "+r"(d[0]), "+r"(d[1]), "+r"(d[2]), "+r"(d[3])
                 : "r"(a[0]), "r"(a[1]), "r"(a[2]), "r"(a[3]), "r"(b0), "r"(b1));
}

// ============================ GEMM scheme-B =================================
// C[m,n] = sum_k A[m,k]*B[n,k]
// per 32-k stage: 2x fp16 k16 (Ah*Bh, exact hi) + 2x s8 k32 imma crosses
// (Ar8*Bh8 + Ah8*Br8, shared s32 acc; v = acc_f + cscale*acc_i)
// CTA tile 64(m) x 128(n), 256 threads, occ 2.
// EPI 1: Ch fp16 + Cr8 (x2^16) + Ch8 (x32) planes (+bias)
// EPI 2: fp16 hi plane Ch[n][m] (+bias) -- transposed (for V^T)
// EPI 3: fp32 C[m][n] + per-64-row-tile column softmax stats -> g_cm/g_cz
#define TCT 256

template<int EPI>
__global__ void __launch_bounds__(TCT, 2)
gemm_b(const __half* __restrict__ Ah, const int8_t* __restrict__ Ar8,
       const int8_t* __restrict__ Ah8,
       const __half* __restrict__ Bh, const int8_t* __restrict__ Br8,
       const int8_t* __restrict__ Bh8,
       const float* __restrict__ bias,
       float* __restrict__ C, __half* __restrict__ Ch,
       int8_t* __restrict__ C4, int8_t* __restrict__ C5,
       int K, int lda, int ldb, int ldc,
       long sA, long sB, long sC, float cscale)
{
    constexpr int OFF_AH  = 0;       // 64 x 64B  = 4096
    constexpr int OFF_BH  = 4096;    // 128 x 64B = 8192
    constexpr int OFF_AR  = 12288;   // 64 x 32B  = 2048
    constexpr int OFF_AH8 = 14336;   // 2048
    constexpr int OFF_BR  = 16384;   // 128 x 32B = 4096
    constexpr int OFF_BH8 = 20480;   // 4096
    constexpr int STG     = 24576;

    extern __shared__ __align__(128) char smem[];
    const uint32_t sb = smem_u32(smem);

    const int tid = threadIdx.x;
    const int lid = tid & 31;
    const int wid = tid >> 5;
    const int wm  = wid >> 2;      // 0..1 -> 32 rows each
    const int wn  = wid & 3;       // 0..3 -> 32 cols each

    const long z = blockIdx.z;
    Ah += z * sA; Ar8 += z * sA; Ah8 += z * sA;
    Bh += z * sB; Br8 += z * sB; Bh8 += z * sB;
    if (EPI == 3) C += z * sC;
    else { Ch += z * sC; if (EPI == 1) { C4 += z * sC; C5 += z * sC; } }

    const int m0 = blockIdx.y * 64;
    const int n0 = blockIdx.x * 128;

    const int nstage = K / 32;

    auto issue = [&](int s) {
        const uint32_t base = sb + (s & 1) * STG;
        const int k0 = s * 32;
        // Ah: 256 chunks of 16B
        {
            const int r = tid >> 2, c = tid & 3;
            const uint32_t doff = r * 64 + ((c ^ ((r + (r >> 2)) & 3)) * 16);
            cp16(base + OFF_AH + doff, Ah + (size_t)(m0 + r) * lda + k0 + c * 8);
        }
        // Bh: 512 chunks
#pragma unroll
        for (int i = 0; i < 2; i++) {
            const int chunk = i * 256 + tid;
            const int r = chunk >> 2, c = chunk & 3;
            const uint32_t doff = r * 64 + ((c ^ ((r + (r >> 2)) & 3)) * 16);
            cp16(base + OFF_BH + doff, Bh + (size_t)(n0 + r) * ldb + k0 + c * 8);
        }
        // A int planes: 128 chunks each; threads<128 -> Ar8, >=128 -> Ah8
        {
            const int t = tid & 127;
            const int r = t >> 1, c = t & 1;
            const uint32_t d8 = r * 32 + ((c ^ ((r + (r >> 2)) & 1)) * 16);
            const int8_t* src = (tid < 128) ? Ar8 : Ah8;
            const uint32_t off = (tid < 128) ? OFF_AR : OFF_AH8;
            cp16(base + off + d8, src + (size_t)(m0 + r) * lda + k0 + c * 16);
        }
        // B int planes: 256 chunks each
        {
            const int r = tid >> 1, c = tid & 1;
            const uint32_t d8 = r * 32 + ((c ^ ((r + (r >> 2)) & 1)) * 16);
            cp16(base + OFF_BR  + d8, Br8 + (size_t)(n0 + r) * ldb + k0 + c * 16);
            cp16(base + OFF_BH8 + d8, Bh8 + (size_t)(n0 + r) * ldb + k0 + c * 16);
        }
        cp_commit();
    };

    float acc_f[2][4][4];
    int   acc_i[2][4][4];
#pragma unroll
    for (int a = 0; a < 2; a++)
#pragma unroll
        for (int b = 0; b < 4; b++)
#pragma unroll
            for (int c = 0; c < 4; c++) { acc_f[a][b][c] = 0.f; acc_i[a][b][c] = 0; }

    const int sub   = lid >> 3;
    const int lane7 = lid & 7;
    const int rA = wm * 32 + (sub & 1) * 8 + lane7;
    const int rB = wn * 32 + (sub & 1) * 8 + lane7;
    const int cs = sub >> 1;
    const int swA = (rA + (rA >> 2)) & 3;
    const int swB = (rB + (rB >> 2)) & 3;
    const uint32_t a8off = ((cs ^ ((rA + (rA >> 2)) & 1)) * 16);
    const uint32_t b8off = ((cs ^ ((rB + (rB >> 2)) & 1)) * 16);

    issue(0);
    issue(1);

    for (int s = 0; s < nstage; s++) {
        if (s + 1 < nstage) cp_wait<1>(); else cp_wait<0>();
        __syncthreads();

        const uint32_t stg = sb + (s & 1) * STG;

        // ---- hi*hi in fp16 (2 x k16), exact hi planes ----
#pragma unroll
        for (int kt = 0; kt < 2; kt++) {
            const int ch = 2 * kt + cs;
            const uint32_t aoff = ((ch ^ swA) * 16);
            const uint32_t boff = ((ch ^ swB) * 16);

            uint32_t aH[2][4], bH[2][4];
#pragma unroll
            for (int mf = 0; mf < 2; mf++)
                ldsm4(aH[mf], stg + OFF_AH + (rA + mf * 16) * 64 + aoff);
#pragma unroll
            for (int bg = 0; bg < 2; bg++)
                ldsm4(bH[bg], stg + OFF_BH + (rB + bg * 16) * 64 + boff);

#pragma unroll
            for (int mf = 0; mf < 2; mf++)
#pragma unroll
                for (int nf = 0; nf < 4; nf++)
                    mma16816(acc_f[mf][nf], aH[mf],
                             bH[nf >> 1][nf & 1], bH[nf >> 1][(nf & 1) + 2]);
        }

        // ---- int8 crosses: Ar8*Bh8 + Ah8*Br8, one s32 acc ----
        {
            uint32_t a8[2][4], b8[2][4];
#pragma unroll
            for (int mf = 0; mf < 2; mf++)
                ldsm4(a8[mf], stg + OFF_AR + (rA + mf * 16) * 32 + a8off);
#pragma unroll
            for (int bg = 0; bg < 2; bg++)
                ldsm4(b8[bg], stg + OFF_BH8 + (rB + bg * 16) * 32 + b8off);
#pragma unroll
            for (int mf = 0; mf < 2; mf++)
#pragma unroll
                for (int nf = 0; nf < 4; nf++)
                    mma_s8(acc_i[mf][nf], a8[mf],
                           b8[nf >> 1][nf & 1], b8[nf >> 1][(nf & 1) + 2]);
#pragma unroll
            for (int mf = 0; mf < 2; mf++)
                ldsm4(a8[mf], stg + OFF_AH8 + (rA + mf * 16) * 32 + a8off);
#pragma unroll
            for (int bg = 0; bg < 2; bg++)
                ldsm4(b8[bg], stg + OFF_BR + (rB + bg * 16) * 32 + b8off);
#pragma unroll
            for (int mf = 0; mf < 2; mf++)
#pragma unroll
                for (int nf = 0; nf < 4; nf++)
                    mma_s8(acc_i[mf][nf], a8[mf],
                           b8[nf >> 1][nf & 1], b8[nf >> 1][(nf & 1) + 2]);
        }

        if (s + 2 < nstage) {
            __syncthreads();
            issue(s + 2);
        }
    }

    // -------------------------- epilogue ------------------------------------
#pragma unroll
    for (int mf = 0; mf < 2; mf++) {
#pragma unroll
        for (int nf = 0; nf < 4; nf++) {
            const int m = m0 + wm * 32 + mf * 16 + (lid >> 2);
            const int n = n0 + wn * 32 + nf * 8 + (lid & 3) * 2;
            float v0 = acc_f[mf][nf][0] + cscale * (float)acc_i[mf][nf][0];
            float v1 = acc_f[mf][nf][1] + cscale * (float)acc_i[mf][nf][1];
            float v2 = acc_f[mf][nf][2] + cscale * (float)acc_i[mf][nf][2];
            float v3 = acc_f[mf][nf][3] + cscale * (float)acc_i[mf][nf][3];
            if (EPI == 1 || EPI == 2) {
                const float b0 = bias[n], b1 = bias[n + 1];
                v0 += b0; v1 += b1; v2 += b0; v3 += b1;
            }
            if (EPI == 3) {
                *(float2*)(C + (size_t)m * ldc + n)       = make_float2(v0, v1);
                *(float2*)(C + (size_t)(m + 8) * ldc + n) = make_float2(v2, v3);
            } else if (EPI == 1) {
                const __half h0 = __float2half_rn(v0), h1 = __float2half_rn(v1);
                const __half h2 = __float2half_rn(v2), h3 = __float2half_rn(v3);
                *(__half2*)(Ch + (size_t)m * ldc + n)       = __halves2half2(h0, h1);
                *(__half2*)(Ch + (size_t)(m + 8) * ldc + n) = __halves2half2(h2, h3);
                char2 r0, r1, s0, s1;
                r0.x = q8((v0 - __half2float(h0)) * 65536.f);
                r0.y = q8((v1 - __half2float(h1)) * 65536.f);
                r1.x = q8((v2 - __half2float(h2)) * 65536.f);
                r1.y = q8((v3 - __half2float(h3)) * 65536.f);
                s0.x = q8(v0 * 32.f); s0.y = q8(v1 * 32.f);
                s1.x = q8(v2 * 32.f); s1.y = q8(v3 * 32.f);
                *(char2*)(C4 + (size_t)m * ldc + n)       = r0;
                *(char2*)(C4 + (size_t)(m + 8) * ldc + n) = r1;
                *(char2*)(C5 + (size_t)m * ldc + n)       = s0;
                *(char2*)(C5 + (size_t)(m + 8) * ldc + n) = s1;
            } else {  // EPI 2: transposed fp16 hi
                Ch[(size_t)n * ldc + m]           = __float2half_rn(v0);
                Ch[(size_t)(n + 1) * ldc + m]     = __float2half_rn(v1);
                Ch[(size_t)n * ldc + m + 8]       = __float2half_rn(v2);
                Ch[(size_t)(n + 1) * ldc + m + 8] = __float2half_rn(v3);
            }
        }
    }

    // ---------------- fused column softmax partials (EPI 3) ----------------
    if (EPI == 3) {
        __syncthreads();
        float* st = (float*)smem;           // [2][128][2] = 2KB

        float cm[8], cz[8];
#pragma unroll
        for (int nf = 0; nf < 4; nf++) {
#pragma unroll
            for (int e = 0; e < 2; e++) {
                float mx = NEG_INF;
#pragma unroll
                for (int mf = 0; mf < 2; mf++) {
                    mx = fmaxf(mx, acc_f[mf][nf][e]     + cscale * (float)acc_i[mf][nf][e]);
                    mx = fmaxf(mx, acc_f[mf][nf][e + 2] + cscale * (float)acc_i[mf][nf][e + 2]);
                }
                float zz = 0.f;
#pragma unroll
                for (int mf = 0; mf < 2; mf++) {
                    zz += fast_exp(acc_f[mf][nf][e]     + cscale * (float)acc_i[mf][nf][e]     - mx);
                    zz += fast_exp(acc_f[mf][nf][e + 2] + cscale * (float)acc_i[mf][nf][e + 2] - mx);
                }
                cm[nf * 2 + e] = mx;
                cz[nf * 2 + e] = zz;
            }
        }
#pragma unroll
        for (int off = 4; off < 32; off <<= 1) {
#pragma unroll
            for (int c = 0; c < 8; c++) {
                const float om = __shfl_xor_sync(0xffffffff, cm[c], off);
                const float oz = __shfl_xor_sync(0xffffffff, cz[c], off);
                const float mn = fmaxf(cm[c], om);
                cz[c] = cz[c] * fast_exp(cm[c] - mn) + oz * fast_exp(om - mn);
                cm[c] = mn;
            }
        }
        if ((lid >> 2) == 0) {
#pragma unroll
            for (int nf = 0; nf < 4; nf++)
#pragma unroll
                for (int e = 0; e < 2; e++) {
                    const int col = wn * 32 + nf * 8 + (lid & 3) * 2 + e;
                    st[(wm * 128 + col) * 2 + 0] = cm[nf * 2 + e];
                    st[(wm * 128 + col) * 2 + 1] = cz[nf * 2 + e];
                }
        }
        __syncthreads();
        if (tid < 128) {
            const float m0v = st[tid * 2],         z0v = st[tid * 2 + 1];
            const float m1v = st[(128 + tid) * 2], z1v = st[(128 + tid) * 2 + 1];
            const float mn = fmaxf(m0v, m1v);
            const float zz = z0v * fast_exp(m0v - mn) + z1v * fast_exp(m1v - mn);
            const size_t o = ((size_t)blockIdx.y * BATCH + blockIdx.z) * SEQ + n0 + tid;
            g_cm[o] = mn;
            g_cz[o] = zz;
        }
    }
}

// ============================ PV GEMM (R8-proven, fp16 single MMA) ===========
__global__ void __launch_bounds__(TCT, 2)
gemm_pv(const __half* __restrict__ Ah, const __half* __restrict__ Bh,
        float* __restrict__ C,
        int K, int lda, int ldb, int ldc, long sA, long sB, long sC)
{
    constexpr int OFF_BH = 8192;
    constexpr int STG    = 16384;

    extern __shared__ __align__(128) char smem[];
    const uint32_t sb = smem_u32(smem);

    const int tid = threadIdx.x;
    const int lid = tid & 31;
    const int wid = tid >> 5;
    const int wm  = wid >> 2;
    const int wn  = wid & 3;

    const long z = blockIdx.z;
    Ah += z * sA; Bh += z * sB; C += z * sC;

    const int m0 = blockIdx.y * 128;
    const int n0 = blockIdx.x * 128;
    const int nstage = K / 32;

    auto issue = [&](int s) {
        const uint32_t base = sb + (s & 1) * STG;
        const int k0 = s * 32;
#pragma unroll
        for (int i = 0; i < 2; i++) {
            const int chunk = i * 256 + tid;
            const int r = chunk >> 2, c = chunk & 3;
            const uint32_t doff = r * 64 + ((c ^ ((r + (r >> 2)) & 3)) * 16);
            cp16(base + doff,          Ah + (size_t)(m0 + r) * lda + k0 + c * 8);
            cp16(base + OFF_BH + doff, Bh + (size_t)(n0 + r) * ldb + k0 + c * 8);
        }
        cp_commit();
    };

    float acc[4][4][4];
#pragma unroll
    for (int a = 0; a < 4; a++)
#pragma unroll
        for (int b = 0; b < 4; b++)
#pragma unroll
            for (int c = 0; c < 4; c++) acc[a][b][c] = 0.f;

    const int sub   = lid >> 3;
    const int lane7 = lid & 7;
    const int rA = wm * 64 + (sub & 1) * 8 + lane7;
    const int rB = wn * 32 + (sub & 1) * 8 + lane7;
    const int cs = sub >> 1;
    const int swA = (rA + (rA >> 2)) & 3;
    const int swB = (rB + (rB >> 2)) & 3;

    issue(0);
    issue(1);

    for (int s = 0; s < nstage; s++) {
        if (s + 1 < nstage) cp_wait<1>(); else cp_wait<0>();
        __syncthreads();

        const uint32_t stg = sb + (s & 1) * STG;
#pragma unroll
        for (int kt = 0; kt < 2; kt++) {
            const int ch = 2 * kt + cs;
            uint32_t aH[4][4], bH[2][4];
#pragma unroll
            for (int mf = 0; mf < 4; mf++)
                ldsm4(aH[mf], stg + (rA + mf * 16) * 64 + ((ch ^ swA) * 16));
#pragma unroll
            for (int bg = 0; bg < 2; bg++)
                ldsm4(bH[bg], stg + OFF_BH + (rB + bg * 16) * 64 + ((ch ^ swB) * 16));
#pragma unroll
            for (int mf = 0; mf < 4; mf++)
#pragma unroll
                for (int nf = 0; nf < 4; nf++)
                    mma16816(acc[mf][nf], aH[mf],
                             bH[nf >> 1][nf & 1], bH[nf >> 1][(nf & 1) + 2]);
        }

        if (s + 2 < nstage) {
            __syncthreads();
            issue(s + 2);
        }
    }

#pragma unroll
    for (int mf = 0; mf < 4; mf++)
#pragma unroll
        for (int nf = 0; nf < 4; nf++) {
            const int m = m0 + wm * 64 + mf * 16 + (lid >> 2);
            const int n = n0 + wn * 32 + nf * 8 + (lid & 3) * 2;
            *(float2*)(C + (size_t)m * ldc + n) =
                make_float2(acc[mf][nf][0], acc[mf][nf][1]);
            *(float2*)(C + (size_t)(m + 8) * ldc + n) =
                make_float2(acc[mf][nf][2], acc[mf][nf][3]);
        }
}

// ---------------------------------------------------------------------------
// fp32 -> fp16 hi + int8 residual (scale sr) + int8 hi (scale sh)
__global__ void __launch_bounds__(256)
split_in(const float* __restrict__ src, __half* __restrict__ h,
         int8_t* __restrict__ r8, int8_t* __restrict__ h8,
         float sr, float sh, int n4)
{
    const int i = blockIdx.x * 256 + threadIdx.x;
    if (i >= n4) return;
    const float4 v = ((const float4*)src)[i];
    float vv[4] = {v.x, v.y, v.z, v.w};
    __half hh[4]; char rr[4], ss[4];
#pragma unroll
    for (int e = 0; e < 4; e++) {
        hh[e] = __float2half_rn(vv[e]);
        rr[e] = q8((vv[e] - __half2float(hh[e])) * sr);
        ss[e] = q8(vv[e] * sh);
    }
    ((__half2*)h)[i * 2]     = __halves2half2(hh[0], hh[1]);
    ((__half2*)h)[i * 2 + 1] = __halves2half2(hh[2], hh[3]);
    *(char4*)(r8 + (size_t)i * 4) = make_char4(rr[0], rr[1], rr[2], rr[3]);
    *(char4*)(h8 + (size_t)i * 4) = make_char4(ss[0], ss[1], ss[2], ss[3]);
}

// ---------------------------------------------------------------------------
__global__ void __launch_bounds__(256)
combine_stats()
{
    const int i = blockIdx.x * 256 + threadIdx.x;
    float m = NEG_INF;
#pragma unroll 8
    for (int t = 0; t < NTILE; t++)
        m = fmaxf(m, g_cm[(size_t)t * BATCH * SEQ + i]);
    float zz = 0.f;
#pragma unroll 8
    for (int t = 0; t < NTILE; t++) {
        const size_t o = (size_t)t * BATCH * SEQ + i;
        zz += g_cz[o] * fast_exp(g_cm[o] - m);
    }
    g_m[i]  = m;
    g_rz[i] = 1.0f / zz;
}

// ---------------------------------------------------------------------------
// P = exp(S - m_k) * rz_k  -> single fp16 plane
__global__ void __launch_bounds__(256)
ppass()
{
    const int b = blockIdx.z;
    const size_t idx = ((size_t)blockIdx.x * 256 + threadIdx.x) * 4;
    const int k = (int)(idx & (SEQ - 1));

    const float4 s4 = *(const float4*)(g_S + (size_t)b * SEQ * SEQ + idx);
    const float4 m4 = *(const float4*)(g_m  + (size_t)b * SEQ + k);
    const float4 r4 = *(const float4*)(g_rz + (size_t)b * SEQ + k);

    __half h0 = __float2half_rn(fast_exp(s4.x - m4.x) * r4.x);
    __half h1 = __float2half_rn(fast_exp(s4.y - m4.y) * r4.y);
    __half h2 = __float2half_rn(fast_exp(s4.z - m4.z) * r4.z);
    __half h3 = __float2half_rn(fast_exp(s4.w - m4.w) * r4.w);

    const size_t o2 = ((size_t)b * SEQ * SEQ + idx) / 2;
    ((__half2*)g_Ph)[o2]     = __halves2half2(h0, h1);
    ((__half2*)g_Ph)[o2 + 1] = __halves2half2(h2, h3);
}

// ---------------------------------------------------------------------------
extern "C" void kernel_launch(void* const* d_in, const int* in_sizes, int n_in,
                              void* d_out, int out_size)
{
    const float* X  = (const float*)d_in[0];
    const float* Wq = (const float*)d_in[1];
    const float* bq = (const float*)d_in[2];
    const float* Wk = (const float*)d_in[3];
    const float* bk = (const float*)d_in[4];
    const float* Wv = (const float*)d_in[5];
    const float* bv = (const float*)d_in[6];
    float* out = (float*)d_out;

    __half *pXh, *pWh, *pQh, *pKh, *pVth, *pPh;
    int8_t *pXr8, *pXh8, *pWr8, *pWh8, *pQr8, *pQh8, *pKr8, *pKh8;
    float  *pS;
    cudaGetSymbolAddress((void**)&pXh,  g_Xh);
    cudaGetSymbolAddress((void**)&pXr8, g_Xr8);
    cudaGetSymbolAddress((void**)&pXh8, g_Xh8);
    cudaGetSymbolAddress((void**)&pWh,  g_Wh);
    cudaGetSymbolAddress((void**)&pWr8, g_Wr8);
    cudaGetSymbolAddress((void**)&pWh8, g_Wh8);
    cudaGetSymbolAddress((void**)&pQh,  g_Qh);
    cudaGetSymbolAddress((void**)&pQr8, g_Qr8);
    cudaGetSymbolAddress((void**)&pQh8, g_Qh8);
    cudaGetSymbolAddress((void**)&pKh,  g_Kh);
    cudaGetSymbolAddress((void**)&pKr8, g_Kr8);
    cudaGetSymbolAddress((void**)&pKh8, g_Kh8);
    cudaGetSymbolAddress((void**)&pVth, g_Vth);
    cudaGetSymbolAddress((void**)&pPh,  g_Ph);
    cudaGetSymbolAddress((void**)&pS,   g_S);

    cudaFuncSetAttribute((const void*)gemm_b<1>, cudaFuncAttributeMaxDynamicSharedMemorySize, 49152);
    cudaFuncSetAttribute((const void*)gemm_b<2>, cudaFuncAttributeMaxDynamicSharedMemorySize, 49152);
    cudaFuncSetAttribute((const void*)gemm_b<3>, cudaFuncAttributeMaxDynamicSharedMemorySize, 49152);
    cudaFuncSetAttribute((const void*)gemm_pv,   cudaFuncAttributeMaxDynamicSharedMemorySize, 32768);

    const dim3 blk(TCT);
    const int WSZ = DIM * DIM;

    // splits: X (sr=2^15, sh=16), W (sr=2^22, sh=2048)
    split_in<<<(MTOT * DIM / 4 + 255) / 256, 256>>>(X, pXh, pXr8, pXh8,
                                                    32768.f, 16.f, MTOT * DIM / 4);
    split_in<<<(WSZ / 4 + 255) / 256, 256>>>(Wq, pWh,           pWr8,           pWh8,
                                             4194304.f, 2048.f, WSZ / 4);
    split_in<<<(WSZ / 4 + 255) / 256, 256>>>(Wk, pWh + WSZ,     pWr8 + WSZ,     pWh8 + WSZ,
                                             4194304.f, 2048.f, WSZ / 4);
    split_in<<<(WSZ / 4 + 255) / 256, 256>>>(Wv, pWh + 2 * WSZ, pWr8 + 2 * WSZ, pWh8 + 2 * WSZ,
                                             4194304.f, 2048.f, WSZ / 4);

    // QKV projections (K=512): cross scale = 1/(2^15*2^11) = 1/(16*2^22) = 2^-26
    const float CS_QKV = 1.0f / 67108864.0f;
    const dim3 gQKV(DIM / 128, MTOT / 64, 1);
    gemm_b<1><<<gQKV, blk, 49152>>>(pXh, pXr8, pXh8, pWh,           pWr8,           pWh8,
                                    bq, nullptr, pQh, pQr8, pQh8,
                                    DIM, DIM, DIM, DIM, 0, 0, 0, CS_QKV);
    gemm_b<1><<<gQKV, blk, 49152>>>(pXh, pXr8, pXh8, pWh + WSZ,     pWr8 + WSZ,     pWh8 + WSZ,
                                    bk, nullptr, pKh, pKr8, pKh8,
                                    DIM, DIM, DIM, DIM, 0, 0, 0, CS_QKV);
    gemm_b<2><<<gQKV, blk, 49152>>>(pXh, pXr8, pXh8, pWh + 2 * WSZ, pWr8 + 2 * WSZ, pWh8 + 2 * WSZ,
                                    bv, nullptr, pVth, nullptr, nullptr,
                                    DIM, DIM, DIM, MTOT, 0, 0, 0, CS_QKV);

    // S = Q K^T per batch (K=512): cross scale = 1/(2^16*32) = 2^-21
    const float CS_S = 1.0f / 2097152.0f;
    const dim3 gS(SEQ / 128, SEQ / 64, BATCH);
    gemm_b<3><<<gS, blk, 49152>>>(pQh, pQr8, pQh8, pKh, pKr8, pKh8,
                                  nullptr, pS, nullptr, nullptr, nullptr,
                                  DIM, DIM, DIM, SEQ,
                                  (long)SEQ * DIM, (long)SEQ * DIM, (long)SEQ * SEQ, CS_S);

    // merge partial stats
    combine_stats<<<(BATCH * SEQ) / 256, 256>>>();

    // P = exp(S - m) * rz -> single fp16 plane
    ppass<<<dim3((SEQ * SEQ) / (256 * 4), 1, BATCH), blk>>>();

    // O = P V per batch (K=4096), single fp16 MMA
    const dim3 gPV(DIM / 128, SEQ / 128, BATCH);
    gemm_pv<<<gPV, blk, 32768>>>(pPh, pVth, out, SEQ, SEQ, MTOT, DIM,
                                 (long)SEQ * SEQ, SEQ, (long)SEQ * DIM);
}

// round 11
// speedup vs baseline: 1.8742x; 1.8742x over previous
#include <cuda_runtime.h>
#include <cuda_fp16.h>
#include <math.h>
#include <stdint.h>

#define BATCH 4
#define SEQ   4096
#define DIM   512
#define MTOT  (BATCH * SEQ)
#define NTILE (SEQ / 128)
#define WSZ   (DIM * DIM)
#define NEG_INF __int_as_float(0xff800000)

// ---------------- scratch (static device globals; no allocation) ------------
__device__ __half g_Xh[(size_t)MTOT * DIM],  g_Xl[(size_t)MTOT * DIM];
__device__ __half g_Wh[3][WSZ],              g_Wl[3][WSZ];
__device__ __half g_Qh[(size_t)MTOT * DIM],  g_Ql[(size_t)MTOT * DIM];
__device__ __half g_Kh[(size_t)MTOT * DIM],  g_Kl[(size_t)MTOT * DIM];
__device__ __half g_Vth[(size_t)DIM * MTOT];               // V^T hi plane only
__device__ float  g_S [(size_t)BATCH * SEQ * SEQ];
__device__ __half g_Ph[(size_t)BATCH * SEQ * SEQ];
__device__ float  g_cm[(size_t)NTILE * BATCH * SEQ];
__device__ float  g_cz[(size_t)NTILE * BATCH * SEQ];
__device__ float  g_m [(size_t)BATCH * SEQ];
__device__ float  g_rz[(size_t)BATCH * SEQ];

// ---------------- fast exp on the FMA pipe -----------------------------------
__device__ __forceinline__ float fast_exp(float x) {
    x = fmaxf(x, -80.0f);
    const float y  = x * 1.4426950408889634f;
    const float t  = y + 12582912.0f;
    const int   ni = __float_as_int(t) - 0x4B400000;
    const float f  = y - (t - 12582912.0f);
    float p = 1.3333558146e-3f;
    p = fmaf(p, f, 9.6181291076e-3f);
    p = fmaf(p, f, 5.5504108664e-2f);
    p = fmaf(p, f, 2.4022650696e-1f);
    p = fmaf(p, f, 6.9314718056e-1f);
    p = fmaf(p, f, 1.0f);
    return __int_as_float(__float_as_int(p) + (ni << 23));
}

// ============================ PTX helpers ===================================
__device__ __forceinline__ uint32_t smem_u32(const void* p) {
    uint32_t a;
    asm("{ .reg .u64 t; cvta.to.shared.u64 t, %1; cvt.u32.u64 %0, t; }"
        : "=r"(a) : "l"(p));
    return a;
}
template<int N> __device__ __forceinline__ void cp_wait() {
    asm volatile("cp.async.wait_group %0;" :: "n"(N) : "memory");
}
__device__ __forceinline__ void cp_commit() {
    asm volatile("cp.async.commit_group;" ::: "memory");
}
__device__ __forceinline__ void cp16(uint32_t dst, const void* src) {
    asm volatile("cp.async.cg.shared.global [%0], [%1], 16;"
                 :: "r"(dst), "l"(src) : "memory");
}
__device__ __forceinline__ void ldsm4(uint32_t* r, uint32_t a) {
    asm volatile("ldmatrix.sync.aligned.m8n8.x4.shared.b16 {%0,%1,%2,%3}, [%4];"
                 : "=r"(r[0]), "=r"(r[1]), "=r"(r[2]), "=r"(r[3]) : "r"(a));
}
__device__ __forceinline__ void mma16816(float* d, const uint32_t* a,
                                         uint32_t b0, uint32_t b1) {
    asm volatile("mma.sync.aligned.m16n8k16.row.col.f32.f16.f16.f32 "
                 "{%0,%1,%2,%3},{%4,%5,%6,%7},{%8,%9},{%0,%1,%2,%3};"
                 : "+f"(d[0]), "+f"(d[1]), "+f"(d[2]), "+f"(d[3])
                 : "r"(a[0]), "r"(a[1]), "r"(a[2]), "r"(a[3]), "r"(b0), "r"(b1));
}

// ============================ GEMM (hi/lo fp16) ==============================
// C[m,n] = sum_k A[m,k]*B[n,k]
// ALO/BLO: whether A/B lo planes exist. MMAs: AhBh [+AlBh if ALO] [+AhBl if BLO]
// EPI 0: fp32 C[m][n], no bias                                        (PV)
// EPI 3: fp32 C[m][n] + per-tile column softmax stats -> g_cm/g_cz    (S)
// EPI 4: fused QKV: blockIdx.z selects W plane / bias / output;
//        z<2 -> hi/lo planes to g_Qh/g_Ql or g_Kh/g_Kl; z=2 -> g_Vth transposed
#define TCT 256

template<int EPI, int ALO, int BLO>
__global__ void __launch_bounds__(TCT, 2)
gemm_hl(const __half* __restrict__ Ah, const __half* __restrict__ Al,
        const __half* __restrict__ Bh, const __half* __restrict__ Bl,
        const float* __restrict__ bias0, const float* __restrict__ bias1,
        const float* __restrict__ bias2,
        float* __restrict__ C,
        int K, int lda, int ldb, int ldc,
        long sA, long sB, long sC)
{
    constexpr int OFF_AL = 8192;
    constexpr int OFF_BH = ALO ? 16384 : 8192;
    constexpr int OFF_BL = OFF_BH + 8192;
    constexpr int STG    = 8192 * (2 + ALO + BLO);

    extern __shared__ __align__(128) char smem[];
    const uint32_t sb = smem_u32(smem);

    const int tid = threadIdx.x;
    const int lid = tid & 31;
    const int wid = tid >> 5;
    const int wm  = wid >> 2;
    const int wn  = wid & 3;

    const long z = blockIdx.z;
    const float* bias = bias0;
    if (EPI == 4) {
        // z selects the weight plane; A (X) is shared
        Bh += z * WSZ; if (BLO) Bl += z * WSZ;
        bias = (z == 0) ? bias0 : (z == 1) ? bias1 : bias2;
    } else {
        Ah += z * sA; if (ALO) Al += z * sA;
        Bh += z * sB; if (BLO) Bl += z * sB;
        C += z * sC;
    }

    const int m0 = blockIdx.y * 128;
    const int n0 = blockIdx.x * 128;

    const int nstage = K / 32;

    auto issue = [&](int s) {
        const uint32_t base = sb + (s & 1) * STG;
        const int k0 = s * 32;
#pragma unroll
        for (int i = 0; i < 2; i++) {
            const int chunk = i * 256 + tid;
            const int r = chunk >> 2;
            const int c = chunk & 3;
            const uint32_t doff = r * 64 + ((c ^ ((r + (r >> 2)) & 3)) * 16);
            const size_t ga = (size_t)(m0 + r) * lda + k0 + c * 8;
            const size_t gb = (size_t)(n0 + r) * ldb + k0 + c * 8;
            cp16(base + doff, Ah + ga);
            if (ALO) cp16(base + OFF_AL + doff, Al + ga);
            cp16(base + OFF_BH + doff, Bh + gb);
            if (BLO) cp16(base + OFF_BL + doff, Bl + gb);
        }
        cp_commit();
    };

    float acc[4][4][4];
#pragma unroll
    for (int a = 0; a < 4; a++)
#pragma unroll
        for (int b = 0; b < 4; b++)
#pragma unroll
            for (int c = 0; c < 4; c++) acc[a][b][c] = 0.f;

    const int sub   = lid >> 3;
    const int lane7 = lid & 7;
    const int rA = wm * 64 + (sub & 1) * 8 + lane7;
    const int rB = wn * 32 + (sub & 1) * 8 + lane7;
    const int cs = sub >> 1;
    const int swA = (rA + (rA >> 2)) & 3;
    const int swB = (rB + (rB >> 2)) & 3;

    issue(0);
    issue(1);

    for (int s = 0; s < nstage; s++) {
        if (s + 1 < nstage) cp_wait<1>(); else cp_wait<0>();
        __syncthreads();

        const uint32_t stg = sb + (s & 1) * STG;
#pragma unroll
        for (int kt = 0; kt < 2; kt++) {
            const int ch = 2 * kt + cs;
            const uint32_t aoff = ((ch ^ swA) * 16);
            const uint32_t boff = ((ch ^ swB) * 16);

            uint32_t aH[4][4], bH[2][4];
#pragma unroll
            for (int mf = 0; mf < 4; mf++)
                ldsm4(aH[mf], stg + (rA + mf * 16) * 64 + aoff);
#pragma unroll
            for (int bg = 0; bg < 2; bg++)
                ldsm4(bH[bg], stg + OFF_BH + (rB + bg * 16) * 64 + boff);

            // hi * hi
#pragma unroll
            for (int mf = 0; mf < 4; mf++)
#pragma unroll
                for (int nf = 0; nf < 4; nf++)
                    mma16816(acc[mf][nf], aH[mf],
                             bH[nf >> 1][nf & 1], bH[nf >> 1][(nf & 1) + 2]);

            // lo * hi
            if (ALO) {
                uint32_t aL[4][4];
#pragma unroll
                for (int mf = 0; mf < 4; mf++)
                    ldsm4(aL[mf], stg + OFF_AL + (rA + mf * 16) * 64 + aoff);
#pragma unroll
                for (int mf = 0; mf < 4; mf++)
#pragma unroll
                    for (int nf = 0; nf < 4; nf++)
                        mma16816(acc[mf][nf], aL[mf],
                                 bH[nf >> 1][nf & 1], bH[nf >> 1][(nf & 1) + 2]);
            }

            // hi * lo
            if (BLO) {
                uint32_t bL[2][4];
#pragma unroll
                for (int bg = 0; bg < 2; bg++)
                    ldsm4(bL[bg], stg + OFF_BL + (rB + bg * 16) * 64 + boff);
#pragma unroll
                for (int mf = 0; mf < 4; mf++)
#pragma unroll
                    for (int nf = 0; nf < 4; nf++)
                        mma16816(acc[mf][nf], aH[mf],
                                 bL[nf >> 1][nf & 1], bL[nf >> 1][(nf & 1) + 2]);
            }
        }

        if (s + 2 < nstage) {
            __syncthreads();
            issue(s + 2);
        }
    }

    // -------------------------- epilogue ------------------------------------
#pragma unroll
    for (int mf = 0; mf < 4; mf++) {
#pragma unroll
        for (int nf = 0; nf < 4; nf++) {
            const int m = m0 + wm * 64 + mf * 16 + (lid >> 2);
            const int n = n0 + wn * 32 + nf * 8 + (lid & 3) * 2;
            float v0 = acc[mf][nf][0], v1 = acc[mf][nf][1];
            float v2 = acc[mf][nf][2], v3 = acc[mf][nf][3];
            if (EPI == 4) {
                const float b0 = bias[n], b1 = bias[n + 1];
                v0 += b0; v1 += b1; v2 += b0; v3 += b1;
            }
            if (EPI == 0 || EPI == 3) {
                *(float2*)(C + (size_t)m * ldc + n)       = make_float2(v0, v1);
                *(float2*)(C + (size_t)(m + 8) * ldc + n) = make_float2(v2, v3);
            } else {  // EPI 4
                const __half h0 = __float2half_rn(v0), h1 = __float2half_rn(v1);
                const __half h2 = __float2half_rn(v2), h3 = __float2half_rn(v3);
                if (z < 2) {
                    __half* Ch = (z == 0) ? g_Qh : g_Kh;
                    __half* Cl = (z == 0) ? g_Ql : g_Kl;
                    const __half l0 = __float2half_rn(v0 - __half2float(h0));
                    const __half l1 = __float2half_rn(v1 - __half2float(h1));
                    const __half l2 = __float2half_rn(v2 - __half2float(h2));
                    const __half l3 = __float2half_rn(v3 - __half2float(h3));
                    *(__half2*)(Ch + (size_t)m * DIM + n)       = __halves2half2(h0, h1);
                    *(__half2*)(Ch + (size_t)(m + 8) * DIM + n) = __halves2half2(h2, h3);
                    *(__half2*)(Cl + (size_t)m * DIM + n)       = __halves2half2(l0, l1);
                    *(__half2*)(Cl + (size_t)(m + 8) * DIM + n) = __halves2half2(l2, l3);
                } else {   // V: transposed hi plane
                    g_Vth[(size_t)n * MTOT + m]           = h0;
                    g_Vth[(size_t)(n + 1) * MTOT + m]     = h1;
                    g_Vth[(size_t)n * MTOT + m + 8]       = h2;
                    g_Vth[(size_t)(n + 1) * MTOT + m + 8] = h3;
                }
            }
        }
    }

    // ---------------- fused column softmax partials (EPI 3) ----------------
    if (EPI == 3) {
        __syncthreads();
        float* st = (float*)smem;

        float cm[8], cz[8];
#pragma unroll
        for (int nf = 0; nf < 4; nf++) {
#pragma unroll
            for (int e = 0; e < 2; e++) {
                float mx = NEG_INF;
#pragma unroll
                for (int mf = 0; mf < 4; mf++) {
                    mx = fmaxf(mx, acc[mf][nf][e]);
                    mx = fmaxf(mx, acc[mf][nf][e + 2]);
                }
                float zz = 0.f;
#pragma unroll
                for (int mf = 0; mf < 4; mf++)
                    zz += fast_exp(acc[mf][nf][e] - mx) + fast_exp(acc[mf][nf][e + 2] - mx);
                cm[nf * 2 + e] = mx;
                cz[nf * 2 + e] = zz;
            }
        }
#pragma unroll
        for (int off = 4; off < 32; off <<= 1) {
#pragma unroll
            for (int c = 0; c < 8; c++) {
                const float om = __shfl_xor_sync(0xffffffff, cm[c], off);
                const float oz = __shfl_xor_sync(0xffffffff, cz[c], off);
                const float mn = fmaxf(cm[c], om);
                cz[c] = cz[c] * fast_exp(cm[c] - mn) + oz * fast_exp(om - mn);
                cm[c] = mn;
            }
        }
        if ((lid >> 2) == 0) {
#pragma unroll
            for (int nf = 0; nf < 4; nf++)
#pragma unroll
                for (int e = 0; e < 2; e++) {
                    const int col = wn * 32 + nf * 8 + (lid & 3) * 2 + e;
                    st[(wm * 128 + col) * 2 + 0] = cm[nf * 2 + e];
                    st[(wm * 128 + col) * 2 + 1] = cz[nf * 2 + e];
                }
        }
        __syncthreads();
        if (tid < 128) {
            const float m0v = st[tid * 2],         z0v = st[tid * 2 + 1];
            const float m1v = st[(128 + tid) * 2], z1v = st[(128 + tid) * 2 + 1];
            const float mn = fmaxf(m0v, m1v);
            const float zz = z0v * fast_exp(m0v - mn) + z1v * fast_exp(m1v - mn);
            const size_t o = ((size_t)blockIdx.y * BATCH + blockIdx.z) * SEQ + n0 + tid;
            g_cm[o] = mn;
            g_cz[o] = zz;
        }
    }
}

// ---------------------------------------------------------------------------
// One fused split pass: X then Wq, Wk, Wv (regions by linear float4 index).
#define XN4 (MTOT * DIM / 4)
#define WN4 (WSZ / 4)

__global__ void __launch_bounds__(256)
split_all(const float* __restrict__ X, const float* __restrict__ Wq,
          const float* __restrict__ Wk, const float* __restrict__ Wv)
{
    const int i = blockIdx.x * 256 + threadIdx.x;
    const float* src;
    __half *h, *l;
    int j;
    if (i < XN4)                       { src = X;  h = g_Xh;    l = g_Xl;    j = i; }
    else if (i < XN4 + WN4)            { src = Wq; h = g_Wh[0]; l = g_Wl[0]; j = i - XN4; }
    else if (i < XN4 + 2 * WN4)        { src = Wk; h = g_Wh[1]; l = g_Wl[1]; j = i - XN4 - WN4; }
    else if (i < XN4 + 3 * WN4)        { src = Wv; h = g_Wh[2]; l = g_Wl[2]; j = i - XN4 - 2 * WN4; }
    else return;

    const float4 v = ((const float4*)src)[j];
    float vv[4] = {v.x, v.y, v.z, v.w};
    __half hh[4], ll[4];
#pragma unroll
    for (int e = 0; e < 4; e++) {
        hh[e] = __float2half_rn(vv[e]);
        ll[e] = __float2half_rn(vv[e] - __half2float(hh[e]));
    }
    ((__half2*)h)[j * 2]     = __halves2half2(hh[0], hh[1]);
    ((__half2*)h)[j * 2 + 1] = __halves2half2(hh[2], hh[3]);
    ((__half2*)l)[j * 2]     = __halves2half2(ll[0], ll[1]);
    ((__half2*)l)[j * 2 + 1] = __halves2half2(ll[2], ll[3]);
}

// ---------------------------------------------------------------------------
__global__ void __launch_bounds__(256)
combine_stats()
{
    const int i = blockIdx.x * 256 + threadIdx.x;
    float m = NEG_INF;
#pragma unroll 4
    for (int t = 0; t < NTILE; t++)
        m = fmaxf(m, g_cm[(size_t)t * BATCH * SEQ + i]);
    float zz = 0.f;
#pragma unroll 4
    for (int t = 0; t < NTILE; t++) {
        const size_t o = (size_t)t * BATCH * SEQ + i;
        zz += g_cz[o] * fast_exp(g_cm[o] - m);
    }
    g_m[i]  = m;
    g_rz[i] = 1.0f / zz;
}

// ---------------------------------------------------------------------------
// P = exp(S - m_k) * rz_k  -> single fp16 plane, 8 elems/thread
__global__ void __launch_bounds__(256)
ppass()
{
    const int b = blockIdx.z;
    const size_t idx = ((size_t)blockIdx.x * 256 + threadIdx.x) * 8;
    const int k = (int)(idx & (SEQ - 1));
    const float* Sb = g_S + (size_t)b * SEQ * SEQ + idx;
    const float* mB = g_m  + (size_t)b * SEQ + k;
    const float* rB = g_rz + (size_t)b * SEQ + k;

#pragma unroll
    for (int h = 0; h < 2; h++) {
        const float4 s4 = *(const float4*)(Sb + h * 4);
        const float4 m4 = *(const float4*)(mB + h * 4);
        const float4 r4 = *(const float4*)(rB + h * 4);
        __half h0 = __float2half_rn(fast_exp(s4.x - m4.x) * r4.x);
        __half h1 = __float2half_rn(fast_exp(s4.y - m4.y) * r4.y);
        __half h2 = __float2half_rn(fast_exp(s4.z - m4.z) * r4.z);
        __half h3 = __float2half_rn(fast_exp(s4.w - m4.w) * r4.w);
        const size_t o2 = ((size_t)b * SEQ * SEQ + idx + h * 4) / 2;
        ((__half2*)g_Ph)[o2]     = __halves2half2(h0, h1);
        ((__half2*)g_Ph)[o2 + 1] = __halves2half2(h2, h3);
    }
}

// ---------------------------------------------------------------------------
extern "C" void kernel_launch(void* const* d_in, const int* in_sizes, int n_in,
                              void* d_out, int out_size)
{
    const float* X  = (const float*)d_in[0];
    const float* Wq = (const float*)d_in[1];
    const float* bq = (const float*)d_in[2];
    const float* Wk = (const float*)d_in[3];
    const float* bk = (const float*)d_in[4];
    const float* Wv = (const float*)d_in[5];
    const float* bv = (const float*)d_in[6];
    float* out = (float*)d_out;

    __half *pXh, *pXl, *pWh, *pWl, *pQh, *pQl, *pKh, *pKl, *pVth, *pPh;
    float  *pS;
    cudaGetSymbolAddress((void**)&pXh,  g_Xh);
    cudaGetSymbolAddress((void**)&pXl,  g_Xl);
    cudaGetSymbolAddress((void**)&pWh,  g_Wh);
    cudaGetSymbolAddress((void**)&pWl,  g_Wl);
    cudaGetSymbolAddress((void**)&pQh,  g_Qh);
    cudaGetSymbolAddress((void**)&pQl,  g_Ql);
    cudaGetSymbolAddress((void**)&pKh,  g_Kh);
    cudaGetSymbolAddress((void**)&pKl,  g_Kl);
    cudaGetSymbolAddress((void**)&pVth, g_Vth);
    cudaGetSymbolAddress((void**)&pPh,  g_Ph);
    cudaGetSymbolAddress((void**)&pS,   g_S);

    cudaFuncSetAttribute((const void*)gemm_hl<4,1,1>, cudaFuncAttributeMaxDynamicSharedMemorySize, 65536);
    cudaFuncSetAttribute((const void*)gemm_hl<3,1,1>, cudaFuncAttributeMaxDynamicSharedMemorySize, 65536);
    cudaFuncSetAttribute((const void*)gemm_hl<0,0,0>, cudaFuncAttributeMaxDynamicSharedMemorySize, 32768);

    const dim3 blk(TCT);

    // fused input splits (X + Wq + Wk + Wv)
    const int TOT4 = XN4 + 3 * WN4;
    split_all<<<(TOT4 + 255) / 256, 256>>>(X, Wq, Wk, Wv);

    // fused QKV projections (K=512): one launch, z selects q/k/v
    const dim3 gQKV(DIM / 128, MTOT / 128, 3);
    gemm_hl<4,1,1><<<gQKV, blk, 65536>>>(pXh, pXl, pWh, pWl, bq, bk, bv,
                                         nullptr, DIM, DIM, DIM, DIM, 0, 0, 0);

    // S = Q K^T per batch (K=512), fp32 out + fused column stats partials
    const dim3 gS(SEQ / 128, SEQ / 128, BATCH);
    gemm_hl<3,1,1><<<gS, blk, 65536>>>(pQh, pQl, pKh, pKl, nullptr, nullptr, nullptr,
                                       pS, DIM, DIM, DIM, SEQ,
                                       (long)SEQ * DIM, (long)SEQ * DIM, (long)SEQ * SEQ);

    // merge partial stats
    combine_stats<<<(BATCH * SEQ) / 256, 256>>>();

    // P = exp(S - m) * rz -> single fp16 plane
    ppass<<<dim3((SEQ * SEQ) / (256 * 8), 1, BATCH), blk>>>();

    // O = P V per batch (K=4096), single-MMA path, fp32 out
    const dim3 gPV(DIM / 128, SEQ / 128, BATCH);
    gemm_hl<0,0,0><<<gPV, blk, 32768>>>(pPh, nullptr, pVth, nullptr, nullptr, nullptr, nullptr,
                                        out, SEQ, SEQ, MTOT, DIM,
                                        (long)SEQ * SEQ, SEQ, (long)SEQ * DIM);
}

// round 12
// speedup vs baseline: 1.9230x; 1.0260x over previous
#include <cuda_runtime.h>
#include <cuda_fp16.h>
#include <math.h>
#include <stdint.h>

#define BATCH 4
#define SEQ   4096
#define DIM   512
#define MTOT  (BATCH * SEQ)
#define NTILE (SEQ / 128)
#define WSZ   (DIM * DIM)
#define NEG_INF __int_as_float(0xff800000)

// ---------------- scratch (static device globals; no allocation) ------------
__device__ __half g_Xh[(size_t)MTOT * DIM],  g_Xl[(size_t)MTOT * DIM];
__device__ __half g_Wh[3][WSZ],              g_Wl[3][WSZ];
__device__ __half g_Qh[(size_t)MTOT * DIM],  g_Ql[(size_t)MTOT * DIM];
__device__ __half g_Kh[(size_t)MTOT * DIM],  g_Kl[(size_t)MTOT * DIM];
__device__ __half g_Vth[(size_t)DIM * MTOT];               // V^T hi plane only
__device__ __half g_E [(size_t)BATCH * SEQ * SEQ];         // exp(S - m_tile), fp16
__device__ float  g_cm[(size_t)NTILE * BATCH * SEQ];       // per-tile col max
__device__ float  g_cz[(size_t)NTILE * BATCH * SEQ];       // per-tile col sumexp
__device__ __half g_f [(size_t)BATCH * NTILE * SEQ];       // exp(m_tile-m)*rz

// ---------------- fast exp on the FMA pipe -----------------------------------
__device__ __forceinline__ float fast_exp(float x) {
    x = fmaxf(x, -80.0f);
    const float y  = x * 1.4426950408889634f;
    const float t  = y + 12582912.0f;
    const int   ni = __float_as_int(t) - 0x4B400000;
    const float f  = y - (t - 12582912.0f);
    float p = 1.3333558146e-3f;
    p = fmaf(p, f, 9.6181291076e-3f);
    p = fmaf(p, f, 5.5504108664e-2f);
    p = fmaf(p, f, 2.4022650696e-1f);
    p = fmaf(p, f, 6.9314718056e-1f);
    p = fmaf(p, f, 1.0f);
    return __int_as_float(__float_as_int(p) + (ni << 23));
}

// ============================ PTX helpers ===================================
__device__ __forceinline__ uint32_t smem_u32(const void* p) {
    uint32_t a;
    asm("{ .reg .u64 t; cvta.to.shared.u64 t, %1; cvt.u32.u64 %0, t; }"
        : "=r"(a) : "l"(p));
    return a;
}
template<int N> __device__ __forceinline__ void cp_wait() {
    asm volatile("cp.async.wait_group %0;" :: "n"(N) : "memory");
}
__device__ __forceinline__ void cp_commit() {
    asm volatile("cp.async.commit_group;" ::: "memory");
}
__device__ __forceinline__ void cp16(uint32_t dst, const void* src) {
    asm volatile("cp.async.cg.shared.global [%0], [%1], 16;"
                 :: "r"(dst), "l"(src) : "memory");
}
__device__ __forceinline__ void ldsm4(uint32_t* r, uint32_t a) {
    asm volatile("ldmatrix.sync.aligned.m8n8.x4.shared.b16 {%0,%1,%2,%3}, [%4];"
                 : "=r"(r[0]), "=r"(r[1]), "=r"(r[2]), "=r"(r[3]) : "r"(a));
}
__device__ __forceinline__ void mma16816(float* d, const uint32_t* a,
                                         uint32_t b0, uint32_t b1) {
    asm volatile("mma.sync.aligned.m16n8k16.row.col.f32.f16.f16.f32 "
                 "{%0,%1,%2,%3},{%4,%5,%6,%7},{%8,%9},{%0,%1,%2,%3};"
                 : "+f"(d[0]), "+f"(d[1]), "+f"(d[2]), "+f"(d[3])
                 : "r"(a[0]), "r"(a[1]), "r"(a[2]), "r"(a[3]), "r"(b0), "r"(b1));
}
__device__ __forceinline__ uint32_t hmul2u(uint32_t a, uint32_t b) {
    const __half2 r = __hmul2(*(const __half2*)&a, *(const __half2*)&b);
    return *(const uint32_t*)&r;
}

// ============================ GEMM (hi/lo fp16) ==============================
// C[m,n] = sum_k A[m,k]*B[n,k]
// ALO/BLO: lo planes exist. MMAs: AhBh [+AlBh if ALO] [+AhBl if BLO]
// PVF: multiply A-fragments by fp16 factor table f[k] (preloaded in smem)
// EPI 0: fp32 C[m][n]                                             (PV)
// EPI 3: fp16 E' = exp(acc - m_tilecol) -> Eh; stats -> g_cm/g_cz (S)
// EPI 4: fused QKV: z selects W plane/bias/output; z<2 hi/lo, z=2 V^T
#define TCT 256

template<int EPI, int ALO, int BLO, int PVF>
__global__ void __launch_bounds__(TCT, 2)
gemm_hl(const __half* __restrict__ Ah, const __half* __restrict__ Al,
        const __half* __restrict__ Bh, const __half* __restrict__ Bl,
        const float* __restrict__ bias0, const float* __restrict__ bias1,
        const float* __restrict__ bias2,
        float* __restrict__ C, __half* __restrict__ Eh,
        const __half* __restrict__ fTab,
        int K, int lda, int ldb, int ldc,
        long sA, long sB, long sC)
{
    constexpr int OFF_AL = 8192;
    constexpr int OFF_BH = ALO ? 16384 : 8192;
    constexpr int OFF_BL = OFF_BH + 8192;
    constexpr int STG    = 8192 * (2 + ALO + BLO);
    constexpr int OFF_F  = 2 * STG;            // f table after stage buffers

    extern __shared__ __align__(128) char smem[];
    const uint32_t sb = smem_u32(smem);

    const int tid = threadIdx.x;
    const int lid = tid & 31;
    const int wid = tid >> 5;
    const int wm  = wid >> 2;
    const int wn  = wid & 3;

    const long z = blockIdx.z;
    const float* bias = bias0;
    if (EPI == 4) {
        Bh += z * WSZ; if (BLO) Bl += z * WSZ;
        bias = (z == 0) ? bias0 : (z == 1) ? bias1 : bias2;
    } else {
        Ah += z * sA; if (ALO) Al += z * sA;
        Bh += z * sB; if (BLO) Bl += z * sB;
        if (EPI == 3) Eh += z * sC; else C += z * sC;
    }

    const int m0 = blockIdx.y * 128;
    const int n0 = blockIdx.x * 128;

    // preload f row for this (batch, q-tile) into smem
    if (PVF) {
        const __half* fB = fTab + ((size_t)blockIdx.z * NTILE + blockIdx.y) * SEQ;
#pragma unroll
        for (int i = 0; i < 2; i++) {
            const int c = i * 256 + tid;      // 512 x 8 halves
            *(uint4*)(smem + OFF_F + c * 16) = *(const uint4*)(fB + c * 8);
        }
    }

    const int nstage = K / 32;

    auto issue = [&](int s) {
        const uint32_t base = sb + (s & 1) * STG;
        const int k0 = s * 32;
#pragma unroll
        for (int i = 0; i < 2; i++) {
            const int chunk = i * 256 + tid;
            const int r = chunk >> 2;
            const int c = chunk & 3;
            const uint32_t doff = r * 64 + ((c ^ ((r + (r >> 2)) & 3)) * 16);
            const size_t ga = (size_t)(m0 + r) * lda + k0 + c * 8;
            const size_t gb = (size_t)(n0 + r) * ldb + k0 + c * 8;
            cp16(base + doff, Ah + ga);
            if (ALO) cp16(base + OFF_AL + doff, Al + ga);
            cp16(base + OFF_BH + doff, Bh + gb);
            if (BLO) cp16(base + OFF_BL + doff, Bl + gb);
        }
        cp_commit();
    };

    float acc[4][4][4];
#pragma unroll
    for (int a = 0; a < 4; a++)
#pragma unroll
        for (int b = 0; b < 4; b++)
#pragma unroll
            for (int c = 0; c < 4; c++) acc[a][b][c] = 0.f;

    const int sub   = lid >> 3;
    const int lane7 = lid & 7;
    const int rA = wm * 64 + (sub & 1) * 8 + lane7;
    const int rB = wn * 32 + (sub & 1) * 8 + lane7;
    const int cs = sub >> 1;
    const int swA = (rA + (rA >> 2)) & 3;
    const int swB = (rB + (rB >> 2)) & 3;

    issue(0);
    issue(1);

    for (int s = 0; s < nstage; s++) {
        if (s + 1 < nstage) cp_wait<1>(); else cp_wait<0>();
        __syncthreads();

        const uint32_t stg = sb + (s & 1) * STG;
#pragma unroll
        for (int kt = 0; kt < 2; kt++) {
            const int ch = 2 * kt + cs;
            const uint32_t aoff = ((ch ^ swA) * 16);
            const uint32_t boff = ((ch ^ swB) * 16);

            uint32_t aH[4][4], bH[2][4];
#pragma unroll
            for (int mf = 0; mf < 4; mf++)
                ldsm4(aH[mf], stg + (rA + mf * 16) * 64 + aoff);
#pragma unroll
            for (int bg = 0; bg < 2; bg++)
                ldsm4(bH[bg], stg + OFF_BH + (rB + bg * 16) * 64 + boff);

            if (PVF) {
                const int kb = s * 32 + kt * 16 + (lid & 3) * 2;
                const uint32_t flo = *(const uint32_t*)(smem + OFF_F + kb * 2);
                const uint32_t fhi = *(const uint32_t*)(smem + OFF_F + kb * 2 + 16);
#pragma unroll
                for (int mf = 0; mf < 4; mf++) {
                    aH[mf][0] = hmul2u(aH[mf][0], flo);
                    aH[mf][1] = hmul2u(aH[mf][1], flo);
                    aH[mf][2] = hmul2u(aH[mf][2], fhi);
                    aH[mf][3] = hmul2u(aH[mf][3], fhi);
                }
            }

            // hi * hi
#pragma unroll
            for (int mf = 0; mf < 4; mf++)
#pragma unroll
                for (int nf = 0; nf < 4; nf++)
                    mma16816(acc[mf][nf], aH[mf],
                             bH[nf >> 1][nf & 1], bH[nf >> 1][(nf & 1) + 2]);

            // lo * hi
            if (ALO) {
                uint32_t aL[4][4];
#pragma unroll
                for (int mf = 0; mf < 4; mf++)
                    ldsm4(aL[mf], stg + OFF_AL + (rA + mf * 16) * 64 + aoff);
#pragma unroll
                for (int mf = 0; mf < 4; mf++)
#pragma unroll
                    for (int nf = 0; nf < 4; nf++)
                        mma16816(acc[mf][nf], aL[mf],
                                 bH[nf >> 1][nf & 1], bH[nf >> 1][(nf & 1) + 2]);
            }

            // hi * lo
            if (BLO) {
                uint32_t bL[2][4];
#pragma unroll
                for (int bg = 0; bg < 2; bg++)
                    ldsm4(bL[bg], stg + OFF_BL + (rB + bg * 16) * 64 + boff);
#pragma unroll
                for (int mf = 0; mf < 4; mf++)
#pragma unroll
                    for (int nf = 0; nf < 4; nf++)
                        mma16816(acc[mf][nf], aH[mf],
                                 bL[nf >> 1][nf & 1], bL[nf >> 1][(nf & 1) + 2]);
            }
        }

        if (s + 2 < nstage) {
            __syncthreads();
            issue(s + 2);
        }
    }

    // -------------------------- epilogue ------------------------------------
    if (EPI == 3) {
        // fused column softmax: per-tile col stats + E' = exp(acc - m_col) fp16
        __syncthreads();
        float* st = (float*)smem;           // [2][128][2] = 2KB

        float cm[8], cz[8];
#pragma unroll
        for (int nf = 0; nf < 4; nf++) {
#pragma unroll
            for (int e = 0; e < 2; e++) {
                float mx = NEG_INF;
#pragma unroll
                for (int mf = 0; mf < 4; mf++) {
                    mx = fmaxf(mx, acc[mf][nf][e]);
                    mx = fmaxf(mx, acc[mf][nf][e + 2]);
                }
                float zz = 0.f;
#pragma unroll
                for (int mf = 0; mf < 4; mf++)
                    zz += fast_exp(acc[mf][nf][e] - mx) + fast_exp(acc[mf][nf][e + 2] - mx);
                cm[nf * 2 + e] = mx;
                cz[nf * 2 + e] = zz;
            }
        }
#pragma unroll
        for (int off = 4; off < 32; off <<= 1) {
#pragma unroll
            for (int c = 0; c < 8; c++) {
                const float om = __shfl_xor_sync(0xffffffff, cm[c], off);
                const float oz = __shfl_xor_sync(0xffffffff, cz[c], off);
                const float mn = fmaxf(cm[c], om);
                cz[c] = cz[c] * fast_exp(cm[c] - mn) + oz * fast_exp(om - mn);
                cm[c] = mn;
            }
        }
        if ((lid >> 2) == 0) {
#pragma unroll
            for (int nf = 0; nf < 4; nf++)
#pragma unroll
                for (int e = 0; e < 2; e++) {
                    const int col = wn * 32 + nf * 8 + (lid & 3) * 2 + e;
                    st[(wm * 128 + col) * 2 + 0] = cm[nf * 2 + e];
                    st[(wm * 128 + col) * 2 + 1] = cz[nf * 2 + e];
                }
        }
        __syncthreads();

        // merged (128-row) column max for E'
        float mcol[8];
#pragma unroll
        for (int nf = 0; nf < 4; nf++)
#pragma unroll
            for (int e = 0; e < 2; e++) {
                const int col = wn * 32 + nf * 8 + (lid & 3) * 2 + e;
                mcol[nf * 2 + e] = fmaxf(st[col * 2], st[(128 + col) * 2]);
            }

#pragma unroll
        for (int mf = 0; mf < 4; mf++) {
#pragma unroll
            for (int nf = 0; nf < 4; nf++) {
                const int m = m0 + wm * 64 + mf * 16 + (lid >> 2);
                const int n = n0 + wn * 32 + nf * 8 + (lid & 3) * 2;
                const float m0c = mcol[nf * 2], m1c = mcol[nf * 2 + 1];
                const __half e0 = __float2half_rn(fast_exp(acc[mf][nf][0] - m0c));
                const __half e1 = __float2half_rn(fast_exp(acc[mf][nf][1] - m1c));
                const __half e2 = __float2half_rn(fast_exp(acc[mf][nf][2] - m0c));
                const __half e3 = __float2half_rn(fast_exp(acc[mf][nf][3] - m1c));
                *(__half2*)(Eh + (size_t)m * ldc + n)       = __halves2half2(e0, e1);
                *(__half2*)(Eh + (size_t)(m + 8) * ldc + n) = __halves2half2(e2, e3);
            }
        }

        if (tid < 128) {
            const float m0v = st[tid * 2],         z0v = st[tid * 2 + 1];
            const float m1v = st[(128 + tid) * 2], z1v = st[(128 + tid) * 2 + 1];
            const float mn = fmaxf(m0v, m1v);
            const float zz = z0v * fast_exp(m0v - mn) + z1v * fast_exp(m1v - mn);
            const size_t o = ((size_t)blockIdx.y * BATCH + blockIdx.z) * SEQ + n0 + tid;
            g_cm[o] = mn;
            g_cz[o] = zz;
        }
        return;
    }

#pragma unroll
    for (int mf = 0; mf < 4; mf++) {
#pragma unroll
        for (int nf = 0; nf < 4; nf++) {
            const int m = m0 + wm * 64 + mf * 16 + (lid >> 2);
            const int n = n0 + wn * 32 + nf * 8 + (lid & 3) * 2;
            float v0 = acc[mf][nf][0], v1 = acc[mf][nf][1];
            float v2 = acc[mf][nf][2], v3 = acc[mf][nf][3];
            if (EPI == 4) {
                const float b0 = bias[n], b1 = bias[n + 1];
                v0 += b0; v1 += b1; v2 += b0; v3 += b1;
            }
            if (EPI == 0) {
                *(float2*)(C + (size_t)m * ldc + n)       = make_float2(v0, v1);
                *(float2*)(C + (size_t)(m + 8) * ldc + n) = make_float2(v2, v3);
            } else {  // EPI 4
                const __half h0 = __float2half_rn(v0), h1 = __float2half_rn(v1);
                const __half h2 = __float2half_rn(v2), h3 = __float2half_rn(v3);
                if (z < 2) {
                    __half* Ch = (z == 0) ? g_Qh : g_Kh;
                    __half* Cl = (z == 0) ? g_Ql : g_Kl;
                    const __half l0 = __float2half_rn(v0 - __half2float(h0));
                    const __half l1 = __float2half_rn(v1 - __half2float(h1));
                    const __half l2 = __float2half_rn(v2 - __half2float(h2));
                    const __half l3 = __float2half_rn(v3 - __half2float(h3));
                    *(__half2*)(Ch + (size_t)m * DIM + n)       = __halves2half2(h0, h1);
                    *(__half2*)(Ch + (size_t)(m + 8) * DIM + n) = __halves2half2(h2, h3);
                    *(__half2*)(Cl + (size_t)m * DIM + n)       = __halves2half2(l0, l1);
                    *(__half2*)(Cl + (size_t)(m + 8) * DIM + n) = __halves2half2(l2, l3);
                } else {
                    g_Vth[(size_t)n * MTOT + m]           = h0;
                    g_Vth[(size_t)(n + 1) * MTOT + m]     = h1;
                    g_Vth[(size_t)n * MTOT + m + 8]       = h2;
                    g_Vth[(size_t)(n + 1) * MTOT + m + 8] = h3;
                }
            }
        }
    }
}

// ---------------------------------------------------------------------------
// One fused split pass: X then Wq, Wk, Wv (regions by linear float4 index).
#define XN4 (MTOT * DIM / 4)
#define WN4 (WSZ / 4)

__global__ void __launch_bounds__(256)
split_all(const float* __restrict__ X, const float* __restrict__ Wq,
          const float* __restrict__ Wk, const float* __restrict__ Wv)
{
    const int i = blockIdx.x * 256 + threadIdx.x;
    const float* src;
    __half *h, *l;
    int j;
    if (i < XN4)                       { src = X;  h = g_Xh;    l = g_Xl;    j = i; }
    else if (i < XN4 + WN4)            { src = Wq; h = g_Wh[0]; l = g_Wl[0]; j = i - XN4; }
    else if (i < XN4 + 2 * WN4)        { src = Wk; h = g_Wh[1]; l = g_Wl[1]; j = i - XN4 - WN4; }
    else if (i < XN4 + 3 * WN4)        { src = Wv; h = g_Wh[2]; l = g_Wl[2]; j = i - XN4 - 2 * WN4; }
    else return;

    const float4 v = ((const float4*)src)[j];
    float vv[4] = {v.x, v.y, v.z, v.w};
    __half hh[4], ll[4];
#pragma unroll
    for (int e = 0; e < 4; e++) {
        hh[e] = __float2half_rn(vv[e]);
        ll[e] = __float2half_rn(vv[e] - __half2float(hh[e]));
    }
    ((__half2*)h)[j * 2]     = __halves2half2(hh[0], hh[1]);
    ((__half2*)h)[j * 2 + 1] = __halves2half2(hh[2], hh[3]);
    ((__half2*)l)[j * 2]     = __halves2half2(ll[0], ll[1]);
    ((__half2*)l)[j * 2 + 1] = __halves2half2(ll[2], ll[3]);
}

// ---------------------------------------------------------------------------
// merge per-tile partials -> f[b][t][k] = exp(cm - m) / Z  (fp16)
__global__ void __launch_bounds__(128)
combine_f()
{
    const int i = blockIdx.x * 128 + threadIdx.x;   // over BATCH*SEQ
    const int b = i >> 12;
    const int k = i & (SEQ - 1);

    float m = NEG_INF;
#pragma unroll 8
    for (int t = 0; t < NTILE; t++)
        m = fmaxf(m, g_cm[(size_t)t * BATCH * SEQ + i]);
    float zz = 0.f;
#pragma unroll 8
    for (int t = 0; t < NTILE; t++) {
        const size_t o = (size_t)t * BATCH * SEQ + i;
        zz += g_cz[o] * fast_exp(g_cm[o] - m);
    }
    const float rz = 1.0f / zz;
#pragma unroll 8
    for (int t = 0; t < NTILE; t++) {
        const size_t o = (size_t)t * BATCH * SEQ + i;
        g_f[((size_t)b * NTILE + t) * SEQ + k] =
            __float2half_rn(fast_exp(g_cm[o] - m) * rz);
    }
}

// ---------------------------------------------------------------------------
extern "C" void kernel_launch(void* const* d_in, const int* in_sizes, int n_in,
                              void* d_out, int out_size)
{
    const float* X  = (const float*)d_in[0];
    const float* Wq = (const float*)d_in[1];
    const float* bq = (const float*)d_in[2];
    const float* Wk = (const float*)d_in[3];
    const float* bk = (const float*)d_in[4];
    const float* Wv = (const float*)d_in[5];
    const float* bv = (const float*)d_in[6];
    float* out = (float*)d_out;

    __half *pXh, *pXl, *pWh, *pWl, *pQh, *pQl, *pKh, *pKl, *pVth, *pE, *pF;
    cudaGetSymbolAddress((void**)&pXh,  g_Xh);
    cudaGetSymbolAddress((void**)&pXl,  g_Xl);
    cudaGetSymbolAddress((void**)&pWh,  g_Wh);
    cudaGetSymbolAddress((void**)&pWl,  g_Wl);
    cudaGetSymbolAddress((void**)&pQh,  g_Qh);
    cudaGetSymbolAddress((void**)&pQl,  g_Ql);
    cudaGetSymbolAddress((void**)&pKh,  g_Kh);
    cudaGetSymbolAddress((void**)&pKl,  g_Kl);
    cudaGetSymbolAddress((void**)&pVth, g_Vth);
    cudaGetSymbolAddress((void**)&pE,   g_E);
    cudaGetSymbolAddress((void**)&pF,   g_f);

    cudaFuncSetAttribute((const void*)gemm_hl<4,1,1,0>, cudaFuncAttributeMaxDynamicSharedMemorySize, 65536);
    cudaFuncSetAttribute((const void*)gemm_hl<3,1,1,0>, cudaFuncAttributeMaxDynamicSharedMemorySize, 65536);
    cudaFuncSetAttribute((const void*)gemm_hl<0,0,0,1>, cudaFuncAttributeMaxDynamicSharedMemorySize, 40960);

    const dim3 blk(TCT);

    // fused input splits (X + Wq + Wk + Wv)
    const int TOT4 = XN4 + 3 * WN4;
    split_all<<<(TOT4 + 255) / 256, 256>>>(X, Wq, Wk, Wv);

    // fused QKV projections (K=512): one launch, z selects q/k/v
    const dim3 gQKV(DIM / 128, MTOT / 128, 3);
    gemm_hl<4,1,1,0><<<gQKV, blk, 65536>>>(pXh, pXl, pWh, pWl, bq, bk, bv,
                                           nullptr, nullptr, nullptr,
                                           DIM, DIM, DIM, DIM, 0, 0, 0);

    // S-GEMM per batch (K=512): E' fp16 + per-tile column stats
    const dim3 gS(SEQ / 128, SEQ / 128, BATCH);
    gemm_hl<3,1,1,0><<<gS, blk, 65536>>>(pQh, pQl, pKh, pKl, nullptr, nullptr, nullptr,
                                         nullptr, pE, nullptr,
                                         DIM, DIM, DIM, SEQ,
                                         (long)SEQ * DIM, (long)SEQ * DIM,
                                         (long)SEQ * SEQ);

    // merge partial stats -> f table
    combine_f<<<(BATCH * SEQ) / 128, 128>>>();

    // O = (E' * f) V per batch (K=4096), single MMA + in-fragment f multiply
    const dim3 gPV(DIM / 128, SEQ / 128, BATCH);
    gemm_hl<0,0,0,1><<<gPV, blk, 40960>>>(pE, nullptr, pVth, nullptr,
                                          nullptr, nullptr, nullptr,
                                          out, nullptr, pF,
                                          SEQ, SEQ, MTOT, DIM,
                                          (long)SEQ * SEQ, SEQ, (long)SEQ * DIM);
}